// round 2
// baseline (speedup 1.0000x reference)
#include <cuda_runtime.h>

// HexConv: out[b,n,o] = sum_k fc_in[b,n,k] * W[o,k] + bias[o]
//   fc_in = gather of 7 hex neighbors (64 dims each) from zero-padded 13x17 grid.
// B=2048, NHEX=165 (11x15), HD=64, K=448, OUT=64. All fp32.
//
// One CTA per batch. Padded grid + full W (+bias) staged in SMEM.
// 220 active threads = 55 n-rows x 4 o-cols; per-thread tile 3n x 16o
// (o = ocol*16 + oi covers all 64 channels -- fixes round-1 half-output bug).

#define NHEX   165
#define HD     64
#define OUTD   64
#define PADW   17
#define PADH   13
#define CELLS  (PADH * PADW)     // 221
#define CELL_F4 17               // 68 floats per padded cell (64 data + 4 pad)
#define WS_F4  113               // 452 floats per W row (448 data + 4 pad)
#define THREADS 224

#define PAD_F4_COUNT (CELLS * CELL_F4)   // 3757 float4
#define WS_F4_COUNT  (OUTD * WS_F4)      // 7232 float4
#define SMEM_BYTES   ((PAD_F4_COUNT + WS_F4_COUNT) * 16 + OUTD * 4)

__global__ void __launch_bounds__(THREADS)
hexconv_kernel(const float* __restrict__ x,
               const float* __restrict__ W,
               const float* __restrict__ bias,
               float* __restrict__ out)
{
    extern __shared__ float4 smem[];
    float4* pad4 = smem;                       // padded input grid
    float4* ws4  = smem + PAD_F4_COUNT;        // weights
    float*  bss  = (float*)(smem + PAD_F4_COUNT + WS_F4_COUNT);

    const int tid = threadIdx.x;
    const int b   = blockIdx.x;

    // ---- zero the padded grid ----
    for (int i = tid; i < PAD_F4_COUNT; i += THREADS)
        pad4[i] = make_float4(0.f, 0.f, 0.f, 0.f);
    __syncthreads();

    // ---- fill interior: x[b] is (165,64) contiguous -> 2640 float4 ----
    const float4* xg = (const float4*)(x + (size_t)b * NHEX * HD);
    for (int i = tid; i < NHEX * (HD / 4); i += THREADS) {
        int n  = i >> 4;          // hex index (16 f4 per hex)
        int d4 = i & 15;
        int r  = n / 15;
        int c  = n - r * 15;
        int cell = (r + 1) * PADW + (c + 1);
        pad4[cell * CELL_F4 + d4] = xg[i];
    }

    // ---- stage W: 64 rows of 448 floats (112 f4), padded row stride 113 f4 ----
    const float4* Wg = (const float4*)W;
    for (int i = tid; i < OUTD * 112; i += THREADS) {
        int o  = i / 112;
        int k4 = i - o * 112;
        ws4[o * WS_F4 + k4] = Wg[i];
    }
    if (tid < OUTD) bss[tid] = bias[tid];
    __syncthreads();

    if (tid >= 220) return;   // 55 n-rows x 4 o-cols active

    const int ocol = tid & 3;      // o = ocol*16 + oi, oi in [0,16)
    const int nrow = tid >> 2;     // 0..54 ; n = nrow + 55*ni

    // neighbor cell bases (in float4 units) for the 3 hexes of this thread
    int cb[3][7];
    {
        const int off0[7] = {-17, -16, -1, 0, 1, 17, 18};  // padded row y even
        const int off1[7] = {-18, -17, -1, 0, 1, 16, 17};  // padded row y odd
#pragma unroll
        for (int ni = 0; ni < 3; ni++) {
            int n = nrow + 55 * ni;
            int r = n / 15;
            int c = n - r * 15;
            int base = (r + 1) * PADW + (c + 1);
            bool even = (((r + 1) & 1) == 0);
#pragma unroll
            for (int j = 0; j < 7; j++)
                cb[ni][j] = (base + (even ? off0[j] : off1[j])) * CELL_F4;
        }
    }

    float acc[3][16];
#pragma unroll
    for (int ni = 0; ni < 3; ni++)
#pragma unroll
        for (int oi = 0; oi < 16; oi++)
            acc[ni][oi] = 0.f;

    const int wb = ocol * 16 * WS_F4;   // W row base for oi=0 (row = ocol*16+oi)

#pragma unroll
    for (int j = 0; j < 7; j++) {
        const int c0 = cb[0][j];
        const int c1 = cb[1][j];
        const int c2 = cb[2][j];
        const int wj = wb + j * 16;
#pragma unroll 2
        for (int d4 = 0; d4 < 16; d4++) {
            float4 a0 = pad4[c0 + d4];
            float4 a1 = pad4[c1 + d4];
            float4 a2 = pad4[c2 + d4];
#pragma unroll
            for (int oi = 0; oi < 16; oi++) {
                float4 wv = ws4[wj + oi * WS_F4 + d4];
                acc[0][oi] += a0.x * wv.x + a0.y * wv.y + a0.z * wv.z + a0.w * wv.w;
                acc[1][oi] += a1.x * wv.x + a1.y * wv.y + a1.z * wv.z + a1.w * wv.w;
                acc[2][oi] += a2.x * wv.x + a2.y * wv.y + a2.z * wv.z + a2.w * wv.w;
            }
        }
    }

    // ---- store + bias ----
    float* og = out + (size_t)b * NHEX * HD;
#pragma unroll
    for (int ni = 0; ni < 3; ni++) {
        int n = nrow + 55 * ni;
        float* orow = og + n * HD + ocol * 16;
#pragma unroll
        for (int oi = 0; oi < 16; oi++)
            orow[oi] = acc[ni][oi] + bss[ocol * 16 + oi];
    }
}

extern "C" void kernel_launch(void* const* d_in, const int* in_sizes, int n_in,
                              void* d_out, int out_size)
{
    const float* x    = (const float*)d_in[0];
    const float* W    = (const float*)d_in[1];
    const float* bias = (const float*)d_in[2];
    float* out = (float*)d_out;

    cudaFuncSetAttribute(hexconv_kernel,
                         cudaFuncAttributeMaxDynamicSharedMemorySize,
                         (int)SMEM_BYTES);
    hexconv_kernel<<<2048, THREADS, SMEM_BYTES>>>(x, W, bias, out);
}

// round 4
// speedup vs baseline: 6.3266x; 6.3266x over previous
#include <cuda_runtime.h>
#include <cstdint>

// HexConv as GEMM on legacy tensor cores (mma.sync tf32, no 'a'-gated features):
//   out[m,o] = sum_k A[m,k]*W[o,k] + bias[o];  m = b*165+n (337920 rows = 2640 tiles x 128)
//   A[m, j*64+d] = x[b, hexneighbor_j(n), d]  (0 for pad) -> gathered by cp.async,
//   one K-chunk of 64 == one neighbor j, so each A row-chunk is 256B contiguous (or zero).
// Per CTA: M=128, N=64, K=448 in 7 chunks of 64, double-buffered cp.async pipeline.
// 8 warps = 4(M) x 2(N); warp tile 32x32 = 2x4 m16n8k8 frags. SMEM rows padded to
// 68 floats so fragment LDS (bank = (4*lr+lc)%32) is conflict-free.

#define NHEX   165
#define HD     64
#define OUTD   64
#define MTILE  128
#define NCHUNK 7
#define ASTR   68
#define THREADS 256
#define NUM_TILES 2640

#define A_FLOATS (MTILE * ASTR)          // 8704
#define W_FLOATS (OUTD  * ASTR)          // 4352
#define SMEM_BYTES ((2 * (A_FLOATS + W_FLOATS)) * 4)   // 104448

static __device__ __forceinline__ uint32_t smem_u32(const void* p) {
    uint32_t a;
    asm("{ .reg .u64 t; cvta.to.shared.u64 t, %1; cvt.u32.u64 %0, t; }" : "=r"(a) : "l"(p));
    return a;
}
static __device__ __forceinline__ void cp16(uint32_t dst, const void* src, uint32_t srcsize) {
    asm volatile("cp.async.cg.shared.global [%0], [%1], 16, %2;"
                 :: "r"(dst), "l"(src), "r"(srcsize) : "memory");
}
static __device__ __forceinline__ void cp_commit() {
    asm volatile("cp.async.commit_group;" ::: "memory");
}
template <int N>
static __device__ __forceinline__ void cp_wait() {
    asm volatile("cp.async.wait_group %0;" :: "n"(N) : "memory");
}

static __device__ __forceinline__ void mma_tf32(float* c, const uint32_t* a, const uint32_t* b) {
    asm volatile(
        "mma.sync.aligned.m16n8k8.row.col.f32.tf32.tf32.f32 "
        "{%0,%1,%2,%3}, {%4,%5,%6,%7}, {%8,%9}, {%0,%1,%2,%3};"
        : "+f"(c[0]), "+f"(c[1]), "+f"(c[2]), "+f"(c[3])
        : "r"(a[0]), "r"(a[1]), "r"(a[2]), "r"(a[3]), "r"(b[0]), "r"(b[1]));
}

__global__ void __launch_bounds__(THREADS, 2)
hexconv_mma(const float* __restrict__ x, const float* __restrict__ W,
            const float* __restrict__ bias, float* __restrict__ out)
{
    extern __shared__ float sm[];
    const uint32_t sb = smem_u32(sm);
    const int tid = threadIdx.x;
    const int t   = blockIdx.x;

    // ---- per-thread gather precompute: thread owns A row (tid>>1), half (tid&1) ----
    const int row  = tid >> 1;
    const int half = tid & 1;
    const int m  = t * MTILE + row;
    const int b  = m / NHEX;
    const int n  = m - b * NHEX;
    const int hr = n / 15, hc = n - 15 * hr;
    const int gbase = (hr + 1) * 17 + (hc + 1);
    const bool even = (((hr + 1) & 1) == 0);
    const float* xb = x + (size_t)b * (NHEX * HD);

    const int off0[7] = {-17, -16, -1, 0, 1, 17, 18};
    const int off1[7] = {-18, -17, -1, 0, 1, 16, 17};

    // W loader mapping: thread -> (o = tid>>2, quad group = (tid&3)*4)
    const int wo = tid >> 2;
    const int wq = (tid & 3) * 4;
    const float* wsrc0 = W + wo * 448 + wq * 4;
    const uint32_t wdst0 = sb + 2 * A_FLOATS * 4 + wo * (ASTR * 4) + wq * 16;

    #define LOAD_CHUNK(c, s)                                                    \
    do {                                                                        \
        const int pi = gbase + (even ? off0[c] : off1[c]);                      \
        const int py = pi / 17, px = pi - 17 * py;                              \
        const bool v = (py >= 1 && py <= 11 && px >= 1 && px <= 15);            \
        const float* asrc = v ? (xb + (((py - 1) * 15 + (px - 1)) * HD) + half * 32) : x; \
        const uint32_t vs = v ? 16u : 0u;                                       \
        uint32_t ad = sb + (s) * (A_FLOATS * 4) + row * (ASTR * 4) + half * 128; \
        _Pragma("unroll")                                                       \
        for (int q = 0; q < 8; q++) cp16(ad + q * 16, asrc + q * 4, vs);        \
        const float* wsrc = wsrc0 + (c) * 64;                                   \
        uint32_t wd = wdst0 + (s) * (W_FLOATS * 4);                             \
        _Pragma("unroll")                                                       \
        for (int q = 0; q < 4; q++) cp16(wd + q * 16, wsrc + q * 4, 16u);       \
        cp_commit();                                                            \
    } while (0)

    // ---- warp/lane geometry ----
    const int wid = tid >> 5, lane = tid & 31;
    const int wm = wid & 3;          // M block of 32
    const int wn = wid >> 2;         // N block of 32
    const int lr = lane >> 2, lc = lane & 3;

    float acc[2][4][4];
#pragma unroll
    for (int mf = 0; mf < 2; mf++)
#pragma unroll
        for (int nf = 0; nf < 4; nf++)
#pragma unroll
            for (int i = 0; i < 4; i++) acc[mf][nf][i] = 0.f;

    const uint32_t* Au = (const uint32_t*)sm;
    const uint32_t* Wu = (const uint32_t*)(sm + 2 * A_FLOATS);

    LOAD_CHUNK(0, 0);

#pragma unroll
    for (int c = 0; c < NCHUNK; c++) {
        if (c + 1 < NCHUNK) {
            switch (c + 1) {   // constant chunk index for full unroll of offsets
                case 1: LOAD_CHUNK(1, 1); break;
                case 2: LOAD_CHUNK(2, 0); break;
                case 3: LOAD_CHUNK(3, 1); break;
                case 4: LOAD_CHUNK(4, 0); break;
                case 5: LOAD_CHUNK(5, 1); break;
                case 6: LOAD_CHUNK(6, 0); break;
            }
            cp_wait<1>();
        } else {
            cp_wait<0>();
        }
        __syncthreads();

        const uint32_t* As = Au + (c & 1) * A_FLOATS;
        const uint32_t* Ws = Wu + (c & 1) * W_FLOATS;

#pragma unroll
        for (int kk = 0; kk < 8; kk++) {
            const int k = kk * 8;
            uint32_t a[2][4];
#pragma unroll
            for (int mf = 0; mf < 2; mf++) {
                const int rb = wm * 32 + mf * 16 + lr;
                a[mf][0] = As[rb * ASTR + k + lc];
                a[mf][1] = As[(rb + 8) * ASTR + k + lc];
                a[mf][2] = As[rb * ASTR + k + 4 + lc];
                a[mf][3] = As[(rb + 8) * ASTR + k + 4 + lc];
            }
            uint32_t bf[4][2];
#pragma unroll
            for (int nf = 0; nf < 4; nf++) {
                const int nb = wn * 32 + nf * 8 + lr;
                bf[nf][0] = Ws[nb * ASTR + k + lc];
                bf[nf][1] = Ws[nb * ASTR + k + 4 + lc];
            }
#pragma unroll
            for (int mf = 0; mf < 2; mf++)
#pragma unroll
                for (int nf = 0; nf < 4; nf++)
                    mma_tf32(acc[mf][nf], a[mf], bf[nf]);
        }
        __syncthreads();
    }

    // ---- epilogue: bias + store (no smem needed, acc frags -> STG.64) ----
    const float2* bias2 = (const float2*)bias;
#pragma unroll
    for (int nf = 0; nf < 4; nf++) {
        const int cc = wn * 32 + nf * 8 + 2 * lc;
        const float2 bv = bias2[cc >> 1];
#pragma unroll
        for (int mf = 0; mf < 2; mf++) {
            const int r0 = t * MTILE + wm * 32 + mf * 16 + lr;
            float2 v0, v1;
            v0.x = acc[mf][nf][0] + bv.x;
            v0.y = acc[mf][nf][1] + bv.y;
            v1.x = acc[mf][nf][2] + bv.x;
            v1.y = acc[mf][nf][3] + bv.y;
            *(float2*)(out + (size_t)r0 * OUTD + cc)       = v0;
            *(float2*)(out + (size_t)(r0 + 8) * OUTD + cc) = v1;
        }
    }
}

extern "C" void kernel_launch(void* const* d_in, const int* in_sizes, int n_in,
                              void* d_out, int out_size)
{
    const float* x    = (const float*)d_in[0];
    const float* W    = (const float*)d_in[1];
    const float* bias = (const float*)d_in[2];
    float* out = (float*)d_out;

    cudaFuncSetAttribute(hexconv_mma,
                         cudaFuncAttributeMaxDynamicSharedMemorySize,
                         (int)SMEM_BYTES);
    hexconv_mma<<<NUM_TILES, THREADS, SMEM_BYTES>>>(x, W, bias, out);
}

// round 5
// speedup vs baseline: 8.0367x; 1.2703x over previous
#include <cuda_runtime.h>
#include <cstdint>

// HexConv, persistent-CTA tf32 mma.sync formulation:
//   CTA stages the zero-padded 13x17 hex grid of one batch in SMEM (once) and all
//   of W (once, tf32-rounded). MMA a-fragments gather-LDS directly from the padded
//   grid (no per-chunk A staging). out[n,o] = sum_{c,k} pad[cell(n)+off(c)][k]*W[o,c*64+k].
// 16 warps = 4(N quarters of 16) x 4(M groups); M frags (16 rows) f = wm + 4u, 11 frags
// cover 165 rows (tail masked). K = 7 chunks x 64 (one hex neighbor each) x 8 kk-steps.

#define NHEX   165
#define HD     64
#define OUTD   64
#define NCHUNK 7
#define GSTR   68            // padded-cell stride in floats (68 % 32 == 4 -> clean banks)
#define WSTR   452           // W row stride in floats (452 % 32 == 4)
#define NB     2048
#define THREADS 512
#define GRIDX  152

#define GRID_FLOATS (221 * GSTR)        // 15028 (13*17 cells)
#define W_FLOATS    (OUTD * WSTR)       // 28928
#define SMEM_BYTES  ((GRID_FLOATS + W_FLOATS) * 4)   // 175824

__constant__ int OFF0c[7] = {-17, -16, -1, 0, 1, 17, 18};   // even grid-row offsets

static __device__ __forceinline__ uint32_t smem_u32(const void* p) {
    uint32_t a;
    asm("{ .reg .u64 t; cvta.to.shared.u64 t, %1; cvt.u32.u64 %0, t; }" : "=r"(a) : "l"(p));
    return a;
}
static __device__ __forceinline__ void cp16(uint32_t dst, const void* src) {
    asm volatile("cp.async.cg.shared.global [%0], [%1], 16;" :: "r"(dst), "l"(src) : "memory");
}
static __device__ __forceinline__ void cp_commit() {
    asm volatile("cp.async.commit_group;" ::: "memory");
}
static __device__ __forceinline__ void cp_wait0() {
    asm volatile("cp.async.wait_group 0;" ::: "memory");
}
static __device__ __forceinline__ uint32_t f2tf(float f) {   // round-to-nearest tf32
    uint32_t r;
    asm("cvt.rna.tf32.f32 %0, %1;" : "=r"(r) : "f"(f));
    return r;
}
static __device__ __forceinline__ void mma_tf32(float* c, const uint32_t* a, const uint32_t* b) {
    asm volatile(
        "mma.sync.aligned.m16n8k8.row.col.f32.tf32.tf32.f32 "
        "{%0,%1,%2,%3}, {%4,%5,%6,%7}, {%8,%9}, {%0,%1,%2,%3};"
        : "+f"(c[0]), "+f"(c[1]), "+f"(c[2]), "+f"(c[3])
        : "r"(a[0]), "r"(a[1]), "r"(a[2]), "r"(a[3]), "r"(b[0]), "r"(b[1]));
}

__global__ void __launch_bounds__(THREADS, 1)
hexconv_mma(const float* __restrict__ x, const float* __restrict__ W,
            const float* __restrict__ bias, float* __restrict__ out)
{
    extern __shared__ float sm[];
    float* G  = sm;                      // padded grid (221 cells x 68 floats)
    float* Wm = sm + GRID_FLOATS;        // W (64 x 452 floats), tf32-rounded
    const uint32_t sb = smem_u32(sm);
    const int tid = threadIdx.x;

    // ---- one-time: zero whole padded grid (pad cells stay zero forever) ----
    float4* G4 = (float4*)G;
    for (int i = tid; i < GRID_FLOATS / 4; i += THREADS)
        G4[i] = make_float4(0.f, 0.f, 0.f, 0.f);

    // ---- one-time: stage W with tf32 RNA rounding ----
    const float4* Wg4 = (const float4*)W;
    for (int i = tid; i < OUTD * 112; i += THREADS) {
        int o = i / 112, k4 = i - o * 112;
        float4 v = Wg4[i];
        v.x = __uint_as_float(f2tf(v.x));
        v.y = __uint_as_float(f2tf(v.y));
        v.z = __uint_as_float(f2tf(v.z));
        v.w = __uint_as_float(f2tf(v.w));
        ((float4*)(Wm + o * WSTR))[k4] = v;
    }

    // ---- warp geometry ----
    const int wid = tid >> 5, lane = tid & 31;
    const int wm = wid & 3;        // M group: frags f = wm + 4u
    const int wn = wid >> 2;       // N quarter (16 cols)
    const int lr = lane >> 2, lc = lane & 3;

    // bias preload (2 float2 per thread)
    float2 bv[2];
#pragma unroll
    for (int nf = 0; nf < 2; nf++)
        bv[nf] = ((const float2*)bias)[(wn * 16 + nf * 8 + 2 * lc) >> 1];

    // per-thread fragment row bases: rows n = 16f + h*8 + lr (clamped for loads)
    int bc[3][2];    // padded cell index
    int par[3][2];   // 1 if padded row odd (use off1 = off0 - adj)
#pragma unroll
    for (int u = 0; u < 3; u++) {
        const int f = wm + 4 * u;
#pragma unroll
        for (int h = 0; h < 2; h++) {
            int n = f * 16 + h * 8 + lr;
            if (n > 164) n = 164;
            int hr = n / 15, hc = n - 15 * hr;
            bc[u][h]  = (hr + 1) * 17 + (hc + 1);
            par[u][h] = (hr + 1) & 1;
        }
    }

    // ---- stage first batch ----
    {
        const float* xb = x + (size_t)blockIdx.x * (NHEX * HD);
        __syncthreads();   // zero/W staging visible before async writes land among them
        for (int i = tid; i < NHEX * 16; i += THREADS) {
            int n = i >> 4, d4 = i & 15;
            int hr = n / 15, hc = n - 15 * hr;
            int cell = (hr + 1) * 17 + (hc + 1);
            cp16(sb + (cell * GSTR + d4 * 4) * 4, xb + n * HD + d4 * 4);
        }
        cp_commit();
    }

    for (int b = blockIdx.x; b < NB; b += GRIDX) {
        cp_wait0();
        __syncthreads();   // staged grid visible to all

        float acc[3][2][4];
#pragma unroll
        for (int u = 0; u < 3; u++)
#pragma unroll
            for (int nf = 0; nf < 2; nf++)
#pragma unroll
                for (int i = 0; i < 4; i++) acc[u][nf][i] = 0.f;

#pragma unroll 1
        for (int c = 0; c < NCHUNK; c++) {
            const int off  = OFF0c[c];                    // uniform LDC
            const int adjc = (c < 2 || c > 4) ? 1 : 0;
            int pA[3][2];
#pragma unroll
            for (int u = 0; u < 3; u++)
#pragma unroll
                for (int h = 0; h < 2; h++)
                    pA[u][h] = (bc[u][h] + off - (adjc ? par[u][h] : 0)) * GSTR + lc;

            const float* Wr = Wm + (wn * 16 + lr) * WSTR + c * 64 + lc;
#pragma unroll
            for (int kk = 0; kk < 8; kk++) {
                const int kb = kk * 8;
                uint32_t bb[2][2];
                bb[0][0] = __float_as_uint(Wr[kb]);
                bb[0][1] = __float_as_uint(Wr[kb + 4]);
                bb[1][0] = __float_as_uint(Wr[8 * WSTR + kb]);
                bb[1][1] = __float_as_uint(Wr[8 * WSTR + kb + 4]);
#pragma unroll
                for (int u = 0; u < 3; u++) {
                    if (u < 2 || wm < 3) {     // wm==3 has only 2 frags
                        uint32_t a[4];
                        a[0] = f2tf(G[pA[u][0] + kb]);
                        a[1] = f2tf(G[pA[u][1] + kb]);
                        a[2] = f2tf(G[pA[u][0] + kb + 4]);
                        a[3] = f2tf(G[pA[u][1] + kb + 4]);
                        mma_tf32(acc[u][0], a, bb[0]);
                        mma_tf32(acc[u][1], a, bb[1]);
                    }
                }
            }
        }

        __syncthreads();   // all warps done reading G -> safe to overwrite

        // ---- issue next batch's staging (overlaps with epilogue) ----
        const int bn = b + GRIDX;
        if (bn < NB) {
            const float* xb = x + (size_t)bn * (NHEX * HD);
            for (int i = tid; i < NHEX * 16; i += THREADS) {
                int n = i >> 4, d4 = i & 15;
                int hr = n / 15, hc = n - 15 * hr;
                int cell = (hr + 1) * 17 + (hc + 1);
                cp16(sb + (cell * GSTR + d4 * 4) * 4, xb + n * HD + d4 * 4);
            }
        }
        cp_commit();

        // ---- epilogue: bias + masked stores ----
        float* ob = out + (size_t)b * (NHEX * OUTD);
#pragma unroll
        for (int u = 0; u < 3; u++) {
            if (u < 2 || wm < 3) {
                const int f = wm + 4 * u;
                const int n1 = f * 16 + lr, n2 = n1 + 8;
#pragma unroll
                for (int nf = 0; nf < 2; nf++) {
                    const int cc = wn * 16 + nf * 8 + 2 * lc;
                    if (n1 < NHEX) {
                        float2 v = make_float2(acc[u][nf][0] + bv[nf].x,
                                               acc[u][nf][1] + bv[nf].y);
                        *(float2*)(ob + n1 * OUTD + cc) = v;
                    }
                    if (n2 < NHEX) {
                        float2 v = make_float2(acc[u][nf][2] + bv[nf].x,
                                               acc[u][nf][3] + bv[nf].y);
                        *(float2*)(ob + n2 * OUTD + cc) = v;
                    }
                }
            }
        }
    }
}

extern "C" void kernel_launch(void* const* d_in, const int* in_sizes, int n_in,
                              void* d_out, int out_size)
{
    const float* x    = (const float*)d_in[0];
    const float* W    = (const float*)d_in[1];
    const float* bias = (const float*)d_in[2];
    float* out = (float*)d_out;

    cudaFuncSetAttribute(hexconv_mma,
                         cudaFuncAttributeMaxDynamicSharedMemorySize,
                         (int)SMEM_BYTES);
    hexconv_mma<<<GRIDX, THREADS, SMEM_BYTES>>>(x, W, bias, out);
}

// round 7
// speedup vs baseline: 9.9032x; 1.2322x over previous
#include <cuda_runtime.h>
#include <cstdint>

// HexConv, persistent-CTA tf32 mma.sync, fully vectorized SMEM traffic:
//   CTA stages zero-padded 13x17 grid of one batch (cp.async) + all of W (once).
//   Logical K-permutation: within each 16-k block, mma k-position (kk,lc) holds
//   orig k = 4*lc + 2*kk + {0,1}; both A and B frags then load as float4 (LDS.128).
//   Strides: grid cell = 80 floats, W row = 464 floats (both == 16 mod 32 ->
//   conflict-free 8-lane LDS.128 phases).
// 16 warps = 4(N quarters) x 4(M groups); frags f = wm + 4u (11 frags, tail masked).

#define NHEX   165
#define HD     64
#define OUTD   64
#define NCHUNK 7
#define GSTR   80            // padded-cell stride in floats
#define WSTR   464           // W row stride in floats
#define NB     2048
#define THREADS 512
#define GRIDX  152

#define GRID_FLOATS (221 * GSTR)        // 17680
#define W_FLOATS    (OUTD * WSTR)       // 29696
#define SMEM_BYTES  ((GRID_FLOATS + W_FLOATS) * 4)   // 189504

__constant__ int OFF0c[7] = {-17, -16, -1, 0, 1, 17, 18};   // even grid-row offsets

static __device__ __forceinline__ uint32_t smem_u32(const void* p) {
    uint32_t a;
    asm("{ .reg .u64 t; cvta.to.shared.u64 t, %1; cvt.u32.u64 %0, t; }" : "=r"(a) : "l"(p));
    return a;
}
static __device__ __forceinline__ void cp16(uint32_t dst, const void* src) {
    asm volatile("cp.async.cg.shared.global [%0], [%1], 16;" :: "r"(dst), "l"(src) : "memory");
}
static __device__ __forceinline__ void cp_commit() {
    asm volatile("cp.async.commit_group;" ::: "memory");
}
static __device__ __forceinline__ void cp_wait0() {
    asm volatile("cp.async.wait_group 0;" ::: "memory");
}
static __device__ __forceinline__ uint32_t f2tf(float f) {   // round-to-nearest tf32
    uint32_t r;
    asm("cvt.rna.tf32.f32 %0, %1;" : "=r"(r) : "f"(f));
    return r;
}
static __device__ __forceinline__ void mma_tf32(float* c,
                                                uint32_t a0, uint32_t a1, uint32_t a2, uint32_t a3,
                                                uint32_t b0, uint32_t b1) {
    asm volatile(
        "mma.sync.aligned.m16n8k8.row.col.f32.tf32.tf32.f32 "
        "{%0,%1,%2,%3}, {%4,%5,%6,%7}, {%8,%9}, {%0,%1,%2,%3};"
        : "+f"(c[0]), "+f"(c[1]), "+f"(c[2]), "+f"(c[3])
        : "r"(a0), "r"(a1), "r"(a2), "r"(a3), "r"(b0), "r"(b1));
}
#define FU(v) __float_as_uint(v)

__global__ void __launch_bounds__(THREADS, 1)
hexconv_mma(const float* __restrict__ x, const float* __restrict__ W,
            const float* __restrict__ bias, float* __restrict__ out)
{
    extern __shared__ float sm[];
    float* G  = sm;                      // padded grid (221 cells x 80 floats)
    float* Wm = sm + GRID_FLOATS;        // W (64 x 464 floats), tf32-rounded
    const uint32_t sb = smem_u32(sm);
    const int tid = threadIdx.x;

    // ---- one-time: zero padded grid ----
    float4* G4 = (float4*)G;
    for (int i = tid; i < GRID_FLOATS / 4; i += THREADS)
        G4[i] = make_float4(0.f, 0.f, 0.f, 0.f);

    // ---- one-time: stage W with tf32 RNA rounding ----
    const float4* Wg4 = (const float4*)W;
    for (int i = tid; i < OUTD * 112; i += THREADS) {
        int o = i / 112, k4 = i - o * 112;
        float4 v = Wg4[i];
        v.x = __uint_as_float(f2tf(v.x));
        v.y = __uint_as_float(f2tf(v.y));
        v.z = __uint_as_float(f2tf(v.z));
        v.w = __uint_as_float(f2tf(v.w));
        *(float4*)(Wm + o * WSTR + k4 * 4) = v;
    }

    // ---- warp geometry ----
    const int wid = tid >> 5, lane = tid & 31;
    const int wm = wid & 3;        // M group: frags f = wm + 4u
    const int wn = wid >> 2;       // N quarter (16 cols)
    const int lr = lane >> 2, lc = lane & 3;

    float2 bv[2];
#pragma unroll
    for (int nf = 0; nf < 2; nf++)
        bv[nf] = ((const float2*)bias)[(wn * 16 + nf * 8 + 2 * lc) >> 1];

    // per-thread fragment row bases (clamped): rows n = 16f + h*8 + lr
    int bc[3][2], par[3][2];
#pragma unroll
    for (int u = 0; u < 3; u++) {
        const int f = wm + 4 * u;
#pragma unroll
        for (int h = 0; h < 2; h++) {
            int n = f * 16 + h * 8 + lr;
            if (n > 164) n = 164;
            int hr = n / 15, hc = n - 15 * hr;
            bc[u][h]  = (hr + 1) * 17 + (hc + 1);
            par[u][h] = (hr + 1) & 1;
        }
    }

    // ---- stage first batch ----
    {
        const float* xb = x + (size_t)blockIdx.x * (NHEX * HD);
        __syncthreads();
        for (int i = tid; i < NHEX * 16; i += THREADS) {
            int n = i >> 4, d4 = i & 15;
            int hr = n / 15, hc = n - 15 * hr;
            int cell = (hr + 1) * 17 + (hc + 1);
            cp16(sb + (cell * GSTR + d4 * 4) * 4, xb + n * HD + d4 * 4);
        }
        cp_commit();
    }

    for (int b = blockIdx.x; b < NB; b += GRIDX) {
        cp_wait0();
        __syncthreads();   // staged raw f32 grid visible

        // ---- in-place tf32 RNA rounding of interior cells ----
        for (int i = tid; i < NHEX * 16; i += THREADS) {
            int n = i >> 4, d4 = i & 15;
            int hr = n / 15, hc = n - 15 * hr;
            float4* p = (float4*)(G + ((hr + 1) * 17 + (hc + 1)) * GSTR) + d4;
            float4 v = *p;
            v.x = __uint_as_float(f2tf(v.x));
            v.y = __uint_as_float(f2tf(v.y));
            v.z = __uint_as_float(f2tf(v.z));
            v.w = __uint_as_float(f2tf(v.w));
            *p = v;
        }
        __syncthreads();

        float acc[3][2][4];
#pragma unroll
        for (int u = 0; u < 3; u++)
#pragma unroll
            for (int nf = 0; nf < 2; nf++)
#pragma unroll
                for (int i = 0; i < 4; i++) acc[u][nf][i] = 0.f;

#pragma unroll 1
        for (int c = 0; c < NCHUNK; c++) {
            const int off  = OFF0c[c];
            const int adjc = (c < 2 || c > 4) ? 1 : 0;
            int pA[3][2];
#pragma unroll
            for (int u = 0; u < 3; u++)
#pragma unroll
                for (int h = 0; h < 2; h++)
                    pA[u][h] = (bc[u][h] + off - (adjc ? par[u][h] : 0)) * GSTR + 4 * lc;

            const float* Wp = Wm + (wn * 16 + lr) * WSTR + c * 64 + 4 * lc;

#pragma unroll
            for (int kb = 0; kb < 64; kb += 16) {
                // B frags (n-frag 0 and 1): float4 covers both k-steps of this block
                float4 w0 = *(const float4*)(Wp + kb);
                float4 w1 = *(const float4*)(Wp + 8 * WSTR + kb);
#pragma unroll
                for (int u = 0; u < 3; u++) {
                    if (u < 2 || wm < 3) {
                        float4 v0 = *(const float4*)(G + pA[u][0] + kb);
                        float4 v1 = *(const float4*)(G + pA[u][1] + kb);
                        // k-step 0: orig k = 4lc + {0,1}
                        mma_tf32(acc[u][0], FU(v0.x), FU(v1.x), FU(v0.y), FU(v1.y),
                                 FU(w0.x), FU(w0.y));
                        mma_tf32(acc[u][1], FU(v0.x), FU(v1.x), FU(v0.y), FU(v1.y),
                                 FU(w1.x), FU(w1.y));
                        // k-step 1: orig k = 4lc + {2,3}
                        mma_tf32(acc[u][0], FU(v0.z), FU(v1.z), FU(v0.w), FU(v1.w),
                                 FU(w0.z), FU(w0.w));
                        mma_tf32(acc[u][1], FU(v0.z), FU(v1.z), FU(v0.w), FU(v1.w),
                                 FU(w1.z), FU(w1.w));
                    }
                }
            }
        }

        __syncthreads();   // all warps done reading G

        // ---- issue next batch's staging (overlaps epilogue) ----
        const int bn = b + GRIDX;
        if (bn < NB) {
            const float* xb = x + (size_t)bn * (NHEX * HD);
            for (int i = tid; i < NHEX * 16; i += THREADS) {
                int n = i >> 4, d4 = i & 15;
                int hr = n / 15, hc = n - 15 * hr;
                int cell = (hr + 1) * 17 + (hc + 1);
                cp16(sb + (cell * GSTR + d4 * 4) * 4, xb + n * HD + d4 * 4);
            }
        }
        cp_commit();

        // ---- epilogue: bias + masked stores ----
        float* ob = out + (size_t)b * (NHEX * OUTD);
#pragma unroll
        for (int u = 0; u < 3; u++) {
            if (u < 2 || wm < 3) {
                const int f = wm + 4 * u;
                const int n1 = f * 16 + lr, n2 = n1 + 8;
#pragma unroll
                for (int nf = 0; nf < 2; nf++) {
                    const int cc = wn * 16 + nf * 8 + 2 * lc;
                    if (n1 < NHEX) {
                        float2 v = make_float2(acc[u][nf][0] + bv[nf].x,
                                               acc[u][nf][1] + bv[nf].y);
                        *(float2*)(ob + n1 * OUTD + cc) = v;
                    }
                    if (n2 < NHEX) {
                        float2 v = make_float2(acc[u][nf][2] + bv[nf].x,
                                               acc[u][nf][3] + bv[nf].y);
                        *(float2*)(ob + n2 * OUTD + cc) = v;
                    }
                }
            }
        }
    }
}

extern "C" void kernel_launch(void* const* d_in, const int* in_sizes, int n_in,
                              void* d_out, int out_size)
{
    const float* x    = (const float*)d_in[0];
    const float* W    = (const float*)d_in[1];
    const float* bias = (const float*)d_in[2];
    float* out = (float*)d_out;

    cudaFuncSetAttribute(hexconv_mma,
                         cudaFuncAttributeMaxDynamicSharedMemorySize,
                         (int)SMEM_BYTES);
    hexconv_mma<<<GRIDX, THREADS, SMEM_BYTES>>>(x, W, bias, out);
}

// round 8
// speedup vs baseline: 17.6053x; 1.7777x over previous
#include <cuda_runtime.h>
#include <cuda_fp16.h>
#include <cstdint>

// HexConv, persistent-CTA fp16 mma.sync (m16n8k16, f32 accum):
//   CTA holds zero-padded 13x17 hex grid of one batch in SMEM as fp16 (192 B/cell)
//   and all of W as fp16 (960 B/row). Batch x is LDG-prefetched to registers during
//   the previous batch's compute, then cvt+STS'd (no cp.async, no staging buffer).
//   K-permutation: per 32-k superblock, thread lc owns orig d = 8lc..8lc+7 -> one
//   LDS.128 feeds two m16n8k16 steps; identical map for A and B.
// 16 warps = 4(N quarters of 16) x 4(M groups); frags f = wm + 4u (11 frags, tail masked).

#define NHEX   165
#define HD     64
#define OUTD   64
#define NCHUNK 7
#define CELLB  192           // bytes per padded cell (128 data + 64 pad); ==64 mod 128
#define WROWB  960           // bytes per W row (896 data + 64 pad);       ==64 mod 128
#define NB     2048
#define THREADS 512
#define GRIDX  152

#define G_BYTES (221 * CELLB)           // 42432
#define W_BYTES (OUTD * WROWB)          // 61440
#define SMEM_BYTES (G_BYTES + W_BYTES)  // 103872

__constant__ int OFF0c[7] = {-17, -16, -1, 0, 1, 17, 18};   // even grid-row offsets

static __device__ __forceinline__ uint32_t pk(float a, float b) {
    __half2 h = __floats2half2_rn(a, b);        // low = a, high = b
    return *(uint32_t*)&h;
}
static __device__ __forceinline__ void mma16816(float* c,
                                                uint32_t a0, uint32_t a1, uint32_t a2, uint32_t a3,
                                                uint32_t b0, uint32_t b1) {
    asm volatile(
        "mma.sync.aligned.m16n8k16.row.col.f32.f16.f16.f32 "
        "{%0,%1,%2,%3}, {%4,%5,%6,%7}, {%8,%9}, {%0,%1,%2,%3};"
        : "+f"(c[0]), "+f"(c[1]), "+f"(c[2]), "+f"(c[3])
        : "r"(a0), "r"(a1), "r"(a2), "r"(a3), "r"(b0), "r"(b1));
}

__global__ void __launch_bounds__(THREADS, 1)
hexconv_mma(const float* __restrict__ x, const float* __restrict__ W,
            const float* __restrict__ bias, float* __restrict__ out)
{
    extern __shared__ char smem[];
    char* Gc = smem;                     // padded grid, fp16, 221 cells x 192 B
    char* Wc = smem + G_BYTES;           // W, fp16, 64 rows x 960 B
    const int tid = threadIdx.x;

    // ---- one-time: zero padded grid (pad cells stay zero forever) ----
    for (int i = tid; i < G_BYTES / 16; i += THREADS)
        ((uint4*)Gc)[i] = make_uint4(0, 0, 0, 0);

    // ---- one-time: stage W as fp16 ----
    const float4* Wg4 = (const float4*)W;
    for (int i = tid; i < OUTD * 112; i += THREADS) {
        int o = i / 112, k4 = i - o * 112;
        float4 v = Wg4[i];
        *(uint2*)(Wc + o * WROWB + k4 * 8) = make_uint2(pk(v.x, v.y), pk(v.z, v.w));
    }

    // ---- warp geometry ----
    const int wid = tid >> 5, lane = tid & 31;
    const int wm = wid & 3;        // M group: frags f = wm + 4u
    const int wn = wid >> 2;       // N quarter (16 cols)
    const int lr = lane >> 2, lc = lane & 3;

    float2 bv[2];
#pragma unroll
    for (int nf = 0; nf < 2; nf++)
        bv[nf] = ((const float2*)bias)[(wn * 16 + nf * 8 + 2 * lc) >> 1];

    // per-thread fragment row bases (clamped): rows n = 16f + h*8 + lr
    int bc[3][2], par[3][2];
#pragma unroll
    for (int u = 0; u < 3; u++) {
        const int f = wm + 4 * u;
#pragma unroll
        for (int h = 0; h < 2; h++) {
            int n = f * 16 + h * 8 + lr;
            if (n > 164) n = 164;
            int hr = n / 15, hc = n - 15 * hr;
            bc[u][h]  = (hr + 1) * 17 + (hc + 1);
            par[u][h] = (hr + 1) & 1;
        }
    }

    // ---- register prefetch of batch x (groups of 8 floats; <=3 per thread) ----
    float4 pf[3][2];
    int gdst[3];   // SMEM byte dest per group
#pragma unroll
    for (int j = 0; j < 3; j++) {
        int g = tid + THREADS * j;
        if (g < NHEX * 8) {
            int n = g >> 3, d8 = g & 7;
            int hr = n / 15, hc = n - 15 * hr;
            gdst[j] = ((hr + 1) * 17 + (hc + 1)) * CELLB + d8 * 16;
        } else gdst[j] = -1;
    }
    {
        const float4* xb4 = (const float4*)(x + (size_t)blockIdx.x * (NHEX * HD));
#pragma unroll
        for (int j = 0; j < 3; j++)
            if (gdst[j] >= 0) {
                int g = tid + THREADS * j;
                pf[j][0] = xb4[2 * g];
                pf[j][1] = xb4[2 * g + 1];
            }
    }
    __syncthreads();   // zeroing complete before first STS

    for (int b = blockIdx.x; b < NB; b += GRIDX) {
        // ---- convert prefetched regs -> fp16 grid ----
#pragma unroll
        for (int j = 0; j < 3; j++)
            if (gdst[j] >= 0) {
                uint4 o;
                o.x = pk(pf[j][0].x, pf[j][0].y);
                o.y = pk(pf[j][0].z, pf[j][0].w);
                o.z = pk(pf[j][1].x, pf[j][1].y);
                o.w = pk(pf[j][1].z, pf[j][1].w);
                *(uint4*)(Gc + gdst[j]) = o;
            }
        __syncthreads();   // grid ready

        // ---- prefetch next batch (overlaps with compute) ----
        const int bn = b + GRIDX;
        if (bn < NB) {
            const float4* xb4 = (const float4*)(x + (size_t)bn * (NHEX * HD));
#pragma unroll
            for (int j = 0; j < 3; j++)
                if (gdst[j] >= 0) {
                    int g = tid + THREADS * j;
                    pf[j][0] = xb4[2 * g];
                    pf[j][1] = xb4[2 * g + 1];
                }
        }

        float acc[3][2][4];
#pragma unroll
        for (int u = 0; u < 3; u++)
#pragma unroll
            for (int nf = 0; nf < 2; nf++)
#pragma unroll
                for (int i = 0; i < 4; i++) acc[u][nf][i] = 0.f;

        const char* Wp0 = Wc + (wn * 16 + lr) * WROWB + 16 * lc;

#pragma unroll 1
        for (int c = 0; c < NCHUNK; c++) {
            const int off  = OFF0c[c];
            const int adjc = (c < 2 || c > 4) ? 1 : 0;
            int pA[3][2];
#pragma unroll
            for (int u = 0; u < 3; u++)
#pragma unroll
                for (int h = 0; h < 2; h++)
                    pA[u][h] = (bc[u][h] + off - (adjc ? par[u][h] : 0)) * CELLB + 16 * lc;

#pragma unroll
            for (int sb = 0; sb < 2; sb++) {
                const int cb = c * 128 + sb * 64;
                uint4 w0 = *(const uint4*)(Wp0 + cb);
                uint4 w1 = *(const uint4*)(Wp0 + 8 * WROWB + cb);
#pragma unroll
                for (int u = 0; u < 3; u++) {
                    if (u < 2 || wm < 3) {
                        uint4 va = *(const uint4*)(Gc + pA[u][0] + sb * 64);
                        uint4 vb = *(const uint4*)(Gc + pA[u][1] + sb * 64);
                        // k-step 0: orig d = 8lc + {0..3}
                        mma16816(acc[u][0], va.x, vb.x, va.y, vb.y, w0.x, w0.y);
                        mma16816(acc[u][1], va.x, vb.x, va.y, vb.y, w1.x, w1.y);
                        // k-step 1: orig d = 8lc + {4..7}
                        mma16816(acc[u][0], va.z, vb.z, va.w, vb.w, w0.z, w0.w);
                        mma16816(acc[u][1], va.z, vb.z, va.w, vb.w, w1.z, w1.w);
                    }
                }
            }
        }

        // ---- epilogue: bias + masked stores ----
        float* ob = out + (size_t)b * (NHEX * OUTD);
#pragma unroll
        for (int u = 0; u < 3; u++) {
            if (u < 2 || wm < 3) {
                const int f = wm + 4 * u;
                const int n1 = f * 16 + lr, n2 = n1 + 8;
#pragma unroll
                for (int nf = 0; nf < 2; nf++) {
                    const int cc = wn * 16 + nf * 8 + 2 * lc;
                    if (n1 < NHEX) {
                        float2 v = make_float2(acc[u][nf][0] + bv[nf].x,
                                               acc[u][nf][1] + bv[nf].y);
                        *(float2*)(ob + n1 * OUTD + cc) = v;
                    }
                    if (n2 < NHEX) {
                        float2 v = make_float2(acc[u][nf][2] + bv[nf].x,
                                               acc[u][nf][3] + bv[nf].y);
                        *(float2*)(ob + n2 * OUTD + cc) = v;
                    }
                }
            }
        }
        __syncthreads();   // all warps done reading G before next STS
    }
}

extern "C" void kernel_launch(void* const* d_in, const int* in_sizes, int n_in,
                              void* d_out, int out_size)
{
    const float* x    = (const float*)d_in[0];
    const float* W    = (const float*)d_in[1];
    const float* bias = (const float*)d_in[2];
    float* out = (float*)d_out;

    cudaFuncSetAttribute(hexconv_mma,
                         cudaFuncAttributeMaxDynamicSharedMemorySize,
                         (int)SMEM_BYTES);
    hexconv_mma<<<GRIDX, THREADS, SMEM_BYTES>>>(x, W, bias, out);
}